// round 2
// baseline (speedup 1.0000x reference)
#include <cuda_runtime.h>
#include <cuda_bf16.h>
#include <cstdint>

// Problem constants
#define BATCH 128
#define NSEQ  384
#define MSEQ  384
#define DDIM  128
#define INF_V 1000000.0f

// ---------------------------------------------------------------------------
// Scratch (static __device__ globals — no allocation)
// ---------------------------------------------------------------------------
__device__ float g_D[(size_t)BATCH * NSEQ * MSEQ];   // 75.5 MB pairwise sq dists
__device__ float g_na[BATCH * NSEQ];                 // ||a_i||^2
__device__ float g_nb[BATCH * MSEQ];                 // ||b_j||^2

// ---------------------------------------------------------------------------
// Kernel 1: row norms of a and b
// ---------------------------------------------------------------------------
__global__ void norm_kernel(const float* __restrict__ A, const float* __restrict__ Bm) {
    int idx = blockIdx.x * blockDim.x + threadIdx.x;   // 0 .. 2*BATCH*NSEQ-1
    const float* src;
    float* dst;
    int row;
    if (idx < BATCH * NSEQ) { src = A;  dst = g_na; row = idx; }
    else                    { src = Bm; dst = g_nb; row = idx - BATCH * NSEQ; }
    const float4* p = (const float4*)(src + (size_t)row * DDIM);
    float s = 0.0f;
#pragma unroll
    for (int i = 0; i < DDIM / 4; i++) {
        float4 v = p[i];
        s += v.x * v.x + v.y * v.y + v.z * v.z + v.w * v.w;
    }
    dst[row] = s;
}

// ---------------------------------------------------------------------------
// Kernel 2: batched pairwise distances via tiled fp32 GEMM
// C[i][j] = dot(a_i, b_j) ;  D = na[i] + nb[j] - 2*C
// Tile: BM=128 x BN=128, BK=16, 256 threads, 8x8 microtile.
// ---------------------------------------------------------------------------
#define BM 128
#define BN 128
#define BK 16
#define PAD 132   // row length for smem tiles (avoids 4-way conflicts, float4-aligned)

__global__ __launch_bounds__(256) void dist_kernel(const float* __restrict__ A,
                                                   const float* __restrict__ Bm) {
    __shared__ float As[BK][PAD];
    __shared__ float Bs[BK][PAD];

    const int b = blockIdx.z;
    const int rowTile = blockIdx.y * BM;
    const int colTile = blockIdx.x * BN;

    const float* a  = A  + ((size_t)b * NSEQ + rowTile) * DDIM;
    const float* bb = Bm + ((size_t)b * MSEQ + colTile) * DDIM;

    const int t  = threadIdx.x;           // 0..255
    const int tm = (t / 16) * 8;          // 0,8,...,120
    const int tn = (t % 16) * 8;

    const int q  = t & 3;                 // k-quad 0..3
    const int r0 = t >> 2;                // row 0..63

    float acc[8][8];
#pragma unroll
    for (int x = 0; x < 8; x++)
#pragma unroll
        for (int y = 0; y < 8; y++) acc[x][y] = 0.0f;

    for (int k0 = 0; k0 < DDIM; k0 += BK) {
        // Load + transpose A and B tiles into smem: each thread 2 float4 per matrix.
#pragma unroll
        for (int p = 0; p < 2; p++) {
            int r = r0 + p * 64;
            float4 va = *(const float4*)(a  + (size_t)r * DDIM + k0 + q * 4);
            As[q * 4 + 0][r] = va.x;
            As[q * 4 + 1][r] = va.y;
            As[q * 4 + 2][r] = va.z;
            As[q * 4 + 3][r] = va.w;
            float4 vb = *(const float4*)(bb + (size_t)r * DDIM + k0 + q * 4);
            Bs[q * 4 + 0][r] = vb.x;
            Bs[q * 4 + 1][r] = vb.y;
            Bs[q * 4 + 2][r] = vb.z;
            Bs[q * 4 + 3][r] = vb.w;
        }
        __syncthreads();

#pragma unroll
        for (int kk = 0; kk < BK; kk++) {
            float4 a0 = *(const float4*)&As[kk][tm];
            float4 a1 = *(const float4*)&As[kk][tm + 4];
            float4 b0 = *(const float4*)&Bs[kk][tn];
            float4 b1 = *(const float4*)&Bs[kk][tn + 4];
            float am[8] = {a0.x, a0.y, a0.z, a0.w, a1.x, a1.y, a1.z, a1.w};
            float bn[8] = {b0.x, b0.y, b0.z, b0.w, b1.x, b1.y, b1.z, b1.w};
#pragma unroll
            for (int x = 0; x < 8; x++)
#pragma unroll
                for (int y = 0; y < 8; y++) acc[x][y] += am[x] * bn[y];
        }
        __syncthreads();
    }

    // Epilogue: D = na + nb - 2*ab
    float na[8], nb8[8];
#pragma unroll
    for (int x = 0; x < 8; x++) na[x]  = g_na[b * NSEQ + rowTile + tm + x];
#pragma unroll
    for (int y = 0; y < 8; y++) nb8[y] = g_nb[b * MSEQ + colTile + tn + y];

    float* Dp = g_D + ((size_t)b * NSEQ + rowTile + tm) * MSEQ + colTile + tn;
#pragma unroll
    for (int x = 0; x < 8; x++) {
        float4 o0, o1;
        o0.x = na[x] + nb8[0] - 2.0f * acc[x][0];
        o0.y = na[x] + nb8[1] - 2.0f * acc[x][1];
        o0.z = na[x] + nb8[2] - 2.0f * acc[x][2];
        o0.w = na[x] + nb8[3] - 2.0f * acc[x][3];
        o1.x = na[x] + nb8[4] - 2.0f * acc[x][4];
        o1.y = na[x] + nb8[5] - 2.0f * acc[x][5];
        o1.z = na[x] + nb8[6] - 2.0f * acc[x][6];
        o1.w = na[x] + nb8[7] - 2.0f * acc[x][7];
        *(float4*)(Dp + (size_t)x * MSEQ)     = o0;
        *(float4*)(Dp + (size_t)x * MSEQ + 4) = o1;
    }
}

// ---------------------------------------------------------------------------
// Kernel 3: soft-DTW anti-diagonal wavefront DP. One CTA per batch.
// R[(N+1)x(M+1)]: R[0][0]=0, borders INF.
// R[i][j] = D[i-1][j-1] + softmin(R[i-1][j-1], R[i-1][j], R[i][j-1])
// Diagonal k holds cells i+j=k; three rotating smem rows indexed by column j.
//   up   = prev1[j], left = prev1[j-1], diag = prev2[j-1]
// ---------------------------------------------------------------------------
__global__ __launch_bounds__(MSEQ) void dtw_kernel(float* __restrict__ out) {
    __shared__ float buf[3][MSEQ + 8];   // columns 0..M

    const int b = blockIdx.x;
    const int t = threadIdx.x;           // 0..383
    const int j = t + 1;                 // column 1..384
    const float* __restrict__ Db = g_D + (size_t)b * NSEQ * MSEQ;

    // init: diag0 (prev2): R[0][0]=0 at col 0, rest INF. diag1 (prev1): all INF.
    buf[0][t] = INF_V;
    buf[1][t] = INF_V;
    buf[2][t] = INF_V;
    if (t == 0) {
        buf[0][MSEQ] = INF_V;
        buf[1][MSEQ] = INF_V;
        buf[2][MSEQ] = INF_V;
        buf[0][0] = 0.0f;
    }
    __syncthreads();

    int p2 = 0, p1 = 1, pc = 2;

    // prefetch D for k=2
    float dnext;
    {
        int i = 2 - j;
        dnext = (i >= 1) ? Db[(size_t)(i - 1) * MSEQ + (j - 1)] : 0.0f;
    }

    for (int k = 2; k <= NSEQ + MSEQ; k++) {
        const float dcur = dnext;
        const int i = k - j;
        const bool valid = (i >= 1) && (i <= NSEQ);

        // prefetch next step's D (independent of smem / barrier)
        {
            int i2 = i + 1;
            if (i2 >= 1 && i2 <= NSEQ && k < NSEQ + MSEQ)
                dnext = Db[(size_t)(i2 - 1) * MSEQ + (j - 1)];
        }

        float val;
        if (valid) {
            float rd = buf[p2][j - 1];   // diag
            float ru = buf[p1][j];       // up
            float rl = buf[p1][j - 1];   // left
            float m  = fminf(rd, fminf(ru, rl));
            float s  = __expf(m - rd) + __expf(m - ru) + __expf(m - rl);
            val = dcur + m - __logf(s);
        } else {
            val = INF_V;
        }

        buf[pc][j] = val;
        if (t == 0) buf[pc][0] = INF_V;                 // R[k][0] border
        if (k == NSEQ + MSEQ && t == MSEQ - 1) out[b] = val;  // R[N][M]

        __syncthreads();
        int tmp = p2; p2 = p1; p1 = pc; pc = tmp;
    }
}

// ---------------------------------------------------------------------------
// Launch
// ---------------------------------------------------------------------------
extern "C" void kernel_launch(void* const* d_in, const int* in_sizes, int n_in,
                              void* d_out, int out_size) {
    const float* a = (const float*)d_in[0];
    const float* b = (const float*)d_in[1];
    float* out = (float*)d_out;

    norm_kernel<<<(2 * BATCH * NSEQ) / 256, 256>>>(a, b);

    dim3 gdist(MSEQ / BN, NSEQ / BM, BATCH);   // (3,3,128)
    dist_kernel<<<gdist, 256>>>(a, b);

    dtw_kernel<<<BATCH, MSEQ>>>(out);
}